// round 16
// baseline (speedup 1.0000x reference)
#include <cuda_runtime.h>
#include <cuda_bf16.h>
#include <math.h>
#include <cstdint>

#define BATCH 8192
#define NVRT  778
#define NJO   21
#define NF    135
#define NM    336      /* 21*16 */
#define NN    1008     /* NM*3  */
#define NNP   1024
#define NFC   405      /* NF*3  */
#define PPLD  784
#define KSPLIT 8
#define KSEG  98       /* PPLD / KSPLIT */

#define PFK   160      /* padded K row stride (bf16); 144 touched, tail stays 0 */

// ---------------- scratch (__device__ globals; zero-init; padding never written) ----
__device__ float g_vsh[NVRT * 3];
__device__ float g_Jk[64];
__device__ float g_W2T[NM * PPLD];
__device__ float g_Pp[NFC * PPLD];
__device__ float g_M[NM];
__device__ float g_C0[NNP];               // [1008..1024) stays 0
__device__ float g_Dp[KSPLIT * NF * NNP];
__device__ __nv_bfloat16 g_pfh[BATCH * PFK];   // pf hi  (k=135 -> 1.0; tail 0)
__device__ __nv_bfloat16 g_pfl[BATCH * PFK];   // pf lo
__device__ __nv_bfloat16 g_DhT[NNP * PFK];     // D^T hi: [n][k] (k=135 -> C0; tail 0)
__device__ __nv_bfloat16 g_DlT[NNP * PFK];     // D^T lo

// ================ stage A: vsh+W2T (25)  ||  Pp transpose (1231)  ||  pf split (512) ====
#define PP_BLKS ((NFC * NVRT + 255) / 256)
__global__ void k_A(const float* __restrict__ us, const float* __restrict__ sd,
                    const float* __restrict__ vt, const float* __restrict__ Jr,
                    const float* __restrict__ wg, const float* __restrict__ pd,
                    const float* __restrict__ theta) {
    int t = threadIdx.x;
    if (blockIdx.x < 25) {
        __shared__ float jrs[32 * 21];
        __shared__ float wgs[32 * 17];
        int v0 = blockIdx.x * 32;
        int nv = NVRT - v0; if (nv > 32) nv = 32;
        for (int i = t; i < nv * 21; i += 256) jrs[i] = Jr[v0 * 21 + i];
        for (int i = t; i < nv * 16; i += 256) {
            int vl = i >> 4, j = i & 15;
            wgs[vl * 17 + j] = wg[(v0 + vl) * 16 + j];
        }
        for (int i = t; i < nv * 3; i += 256) {
            int g = v0 * 3 + i;
            float s = vt[g];
#pragma unroll
            for (int q = 0; q < 10; q++) s += us[q] * sd[q * 2334 + g];
            g_vsh[g] = s;
        }
        __syncthreads();
        for (int i = t; i < NM * 32; i += 256) {
            int vl = i & 31, m = i >> 5;
            int v = v0 + vl;
            if (v < NVRT)
                g_W2T[m * PPLD + v] = jrs[vl * 21 + (m >> 4)] * wgs[vl * 17 + (m & 15)];
        }
    } else if (blockIdx.x < 25 + PP_BLKS) {
        int idx = (blockIdx.x - 25) * 256 + t;
        if (idx < NFC * NVRT) {
            int fc = idx / NVRT, v = idx - fc * NVRT;
            int f = fc / 3, c = fc - 3 * f;
            g_Pp[fc * PPLD + v] = pd[f * 2334 + 3 * v + c];
        }
    } else {
        int idx = (blockIdx.x - 25 - PP_BLKS) * 256 + t;  // BATCH*16 exact
        int b = idx >> 4, s = idx & 15;
        if (s == 15) {
            g_pfh[b * PFK + 135] = __float2bfloat16(1.0f);
            return;
        }
        const float* th = theta + b * 45 + 3 * s;
        float tx = th[0], ty = th[1], tz = th[2];
        float ax = tx + 1e-8f, ay = ty + 1e-8f, az = tz + 1e-8f;
        float angle = sqrtf(ax * ax + ay * ay + az * az);
        float inv = 1.0f / angle;
        float nx = tx * inv, ny = ty * inv, nz = tz * inv;
        float sh, ch;
        sincosf(0.5f * angle, &sh, &ch);
        float qw = ch, qx = sh * nx, qy = sh * ny, qz = sh * nz;
        float qn = rsqrtf(qw * qw + qx * qx + qy * qy + qz * qz);
        qw *= qn; qx *= qn; qy *= qn; qz *= qn;
        float w2 = qw * qw, x2 = qx * qx, y2 = qy * qy, z2 = qz * qz;
        float wx = qw * qx, wy = qw * qy, wz = qw * qz;
        float xy = qx * qy, xz = qx * qz, yz = qy * qz;
        float o[9];
        o[0] = w2 + x2 - y2 - z2 - 1.0f;
        o[1] = 2.f * (xy - wz);
        o[2] = 2.f * (wy + xz);
        o[3] = 2.f * (wz + xy);
        o[4] = w2 - x2 + y2 - z2 - 1.0f;
        o[5] = 2.f * (yz - wx);
        o[6] = 2.f * (xz - wy);
        o[7] = 2.f * (wx + yz);
        o[8] = w2 - x2 - y2 + z2 - 1.0f;
#pragma unroll
        for (int e = 0; e < 9; e++) {
            float x = o[e];
            __nv_bfloat16 h = __float2bfloat16(x);
            g_pfh[b * PFK + 9 * s + e] = h;
            g_pfl[b * PFK + 9 * s + e] = __float2bfloat16(x - __bfloat162float(h));
        }
    }
}

// ================ stage B: Jk/M/C0  ||  D split-K partials ====
__global__ void k_B(const float* __restrict__ Jr) {
    int t = threadIdx.x;
    int blk = blockIdx.x;
    if (blk < NM + 63) {
        __shared__ float vs[NVRT * 3];
        __shared__ float red[4][256];
        for (int i = t; i < NVRT * 3; i += 256) vs[i] = g_vsh[i];
        __syncthreads();
        if (blk < NM) {
            int m = blk;
            float sm = 0.f, s0 = 0.f, s1 = 0.f, s2 = 0.f;
            for (int v = t; v < NVRT; v += 256) {
                float w = g_W2T[m * PPLD + v];
                sm += w;
                s0 += w * vs[v * 3 + 0];
                s1 += w * vs[v * 3 + 1];
                s2 += w * vs[v * 3 + 2];
            }
            red[0][t] = sm; red[1][t] = s0; red[2][t] = s1; red[3][t] = s2;
            __syncthreads();
            for (int o = 128; o > 0; o >>= 1) {
                if (t < o) {
                    red[0][t] += red[0][t + o]; red[1][t] += red[1][t + o];
                    red[2][t] += red[2][t + o]; red[3][t] += red[3][t + o];
                }
                __syncthreads();
            }
            if (t == 0) {
                g_M[m] = red[0][0];
                g_C0[m * 3 + 0] = red[1][0];
                g_C0[m * 3 + 1] = red[2][0];
                g_C0[m * 3 + 2] = red[3][0];
            }
        } else {
            int idx = blk - NM;
            int j = idx / 3, c = idx - 3 * j;
            float s = 0.f;
            for (int v = t; v < NVRT; v += 256) s += vs[v * 3 + c] * Jr[v * 21 + j];
            red[0][t] = s; __syncthreads();
            for (int o = 128; o > 0; o >>= 1) {
                if (t < o) red[0][t] += red[0][t + o];
                __syncthreads();
            }
            if (t == 0) g_Jk[j * 3 + c] = red[0][0];
        }
    } else {
        __shared__ float As[32][33];
        __shared__ float Bs[32][33];
        int b2 = blk - (NM + 63);
        int ks = b2 / 143;
        int rem = b2 - ks * 143;
        int m0 = (rem % 11) * 32;
        int fc0 = (rem / 11) * 32;
        int kbase = ks * KSEG, kend = kbase + KSEG;
        int tx = t & 15, ty = t >> 4;
        float acc[2][2] = {};
        for (int k0 = kbase; k0 < kend; k0 += 32) {
#pragma unroll
            for (int r = 0; r < 4; r++) {
                int e = t + 256 * r; int kk = e & 31, fl = e >> 5;
                int fc = fc0 + fl, k = k0 + kk;
                As[fl][kk] = (fc < NFC && k < kend) ? g_Pp[fc * PPLD + k] : 0.f;
            }
#pragma unroll
            for (int r = 0; r < 4; r++) {
                int e = t + 256 * r; int kk = e & 31, ml = e >> 5;
                int m = m0 + ml, k = k0 + kk;
                Bs[ml][kk] = (m < NM && k < kend) ? g_W2T[m * PPLD + k] : 0.f;
            }
            __syncthreads();
#pragma unroll
            for (int kk = 0; kk < 32; kk++) {
                float a0 = As[ty][kk], a1 = As[ty + 16][kk];
                float b0 = Bs[tx][kk], b1 = Bs[tx + 16][kk];
                acc[0][0] += a0 * b0; acc[0][1] += a0 * b1;
                acc[1][0] += a1 * b0; acc[1][1] += a1 * b1;
            }
            __syncthreads();
        }
#pragma unroll
        for (int i = 0; i < 2; i++) {
            int fc = fc0 + ty + 16 * i;
            if (fc >= NFC) continue;
            int f = fc / 3, c = fc - 3 * f;
#pragma unroll
            for (int jj = 0; jj < 2; jj++) {
                int m = m0 + tx + 16 * jj;
                if (m < NM) g_Dp[(ks * NF + f) * NNP + m * 3 + c] = acc[i][jj];
            }
        }
    }
}

// ================ combine partials + bf16 hi/lo split + transpose (fused) ========
__global__ void k_red2() {
    int idx = blockIdx.x * 256 + threadIdx.x;   // 136*1024 exact
    int k = idx >> 10, n = idx & 1023;
    float x;
    if (k < NF) {
        const int S = NF * NNP;
        x = 0.f;
#pragma unroll
        for (int q = 0; q < KSPLIT; q++) x += g_Dp[q * S + k * NNP + n];
    } else {
        x = g_C0[n];
    }
    __nv_bfloat16 h = __float2bfloat16(x);
    g_DhT[n * PFK + k] = h;
    g_DlT[n * PFK + k] = __float2bfloat16(x - __bfloat162float(h));
}

// ================ giant fused kernel: chain + HMMA GEMM + epilogue ================
// 128 CTAs x 256 threads; CTA owns 64 batches, loops 16 n-chunks of 64 cols.
// Panels: PROW=304 B (76 words; 76 mod 32 = 12 -> ldmatrix rows conflict-free).
// smem bytes:
//   Amat [0, 50176)            64 x 196 floats (chain output; stride 196 avoids bank 0 pileup)
//   Js   [50176, 66560)        64 x 64 floats (joint partials)
//   Ps   [66560, 83968)        64 x 68 floats (chunk P)   (aliased early: ths)
//   AH   [83968, 103424)       64 x 304 B
//   AL   [103424, 122880)
//   BH   [122880, 142336)      (aliased early: pff, 34560 B)
//   BL   [142336, 161792)
#define PROW    304
#define SM_AMAT 0
#define SM_JS   50176
#define SM_PS   66560
#define SM_AH   83968
#define SM_AL   103424
#define SM_BH   122880
#define SM_BL   142336
#define G_SMEM  161792

__device__ __forceinline__ uint32_t s2u(const void* p) {
    uint32_t a;
    asm("{ .reg .u64 t; cvta.to.shared.u64 t, %1; cvt.u32.u64 %0, t; }" : "=r"(a) : "l"(p));
    return a;
}
__device__ __forceinline__ void ldm4(uint32_t* r, uint32_t addr) {
    asm volatile("ldmatrix.sync.aligned.m8n8.x4.shared.b16 {%0,%1,%2,%3}, [%4];"
                 : "=r"(r[0]), "=r"(r[1]), "=r"(r[2]), "=r"(r[3]) : "r"(addr));
}
__device__ __forceinline__ void mmabf(float* c, const uint32_t* a, uint32_t b0, uint32_t b1) {
    asm volatile(
        "mma.sync.aligned.m16n8k16.row.col.f32.bf16.bf16.f32 "
        "{%0,%1,%2,%3}, {%4,%5,%6,%7}, {%8,%9}, {%0,%1,%2,%3};"
        : "+f"(c[0]), "+f"(c[1]), "+f"(c[2]), "+f"(c[3])
        : "r"(a[0]), "r"(a[1]), "r"(a[2]), "r"(a[3]), "r"(b0), "r"(b1));
}

__global__ __launch_bounds__(256, 1)
void k_giant(const float* __restrict__ theta, const float* __restrict__ dq,
             const float* __restrict__ iq, const float* __restrict__ tr,
             float* __restrict__ out) {
    extern __shared__ char smc[];
    float* Amat = (float*)(smc + SM_AMAT);
    float* Js   = (float*)(smc + SM_JS);
    float* Ps   = (float*)(smc + SM_PS);
    char*  AH   = smc + SM_AH;
    char*  AL   = smc + SM_AL;
    char*  BH   = smc + SM_BH;
    char*  BL   = smc + SM_BL;
    float* ths  = Ps;                    // alias (dead before first spill)
    float* pff  = (float*)BH;            // alias (dead before first B stage)
    __shared__ float Jks[48];
    __shared__ float Ms[NM];
    __shared__ float Ts[192];

    int t = threadIdx.x, wid = t >> 5, lane = t & 31;
    int b0 = (int)blockIdx.x * 64;

    // ---- stage inputs + A panels + zero Js ----
    for (int i = t; i < 64 * 45; i += 256) ths[i] = theta[b0 * 45 + i];
    if (t < 48) Jks[t] = g_Jk[t];
    for (int i = t; i < NM; i += 256) Ms[i] = g_M[i];
    if (t >= 64 && t < 256 && t - 64 < 192) Ts[t - 64] = tr[b0 * 3 + (t - 64)];
    for (int i = t; i < 4096; i += 256) Js[i] = 0.f;
    for (int i = t; i < 64 * 18; i += 256) {
        int r = i / 18, c = i - r * 18;
        uint32_t so = (uint32_t)(r * PROW + c * 16);
        uint64_t ga = (uint64_t)(b0 + r) * PFK + c * 8;
        *(uint4*)(AH + so) = *(const uint4*)&g_pfh[ga];
        *(uint4*)(AL + so) = *(const uint4*)&g_pfl[ga];
    }
    __syncthreads();

    // ---- pose features (fp32, for chain): 960 items ----
    for (int it = t; it < 64 * 15; it += 256) {
        int bl = it / 15, i = it - bl * 15;
        const float* th = ths + bl * 45 + 3 * i;
        float tx = th[0], ty = th[1], tz = th[2];
        float ax = tx + 1e-8f, ay = ty + 1e-8f, az = tz + 1e-8f;
        float angle = sqrtf(ax * ax + ay * ay + az * az);
        float inv = 1.0f / angle;
        float nx = tx * inv, ny = ty * inv, nz = tz * inv;
        float sh, ch;
        sincosf(0.5f * angle, &sh, &ch);
        float qw = ch, qx = sh * nx, qy = sh * ny, qz = sh * nz;
        float qn = rsqrtf(qw * qw + qx * qx + qy * qy + qz * qz);
        qw *= qn; qx *= qn; qy *= qn; qz *= qn;
        float w2 = qw * qw, x2 = qx * qx, y2 = qy * qy, z2 = qz * qz;
        float wx = qw * qx, wy = qw * qy, wz = qw * qz;
        float xy = qx * qy, xz = qx * qz, yz = qy * qz;
        float o[9];
        o[0] = w2 + x2 - y2 - z2 - 1.0f;
        o[1] = 2.f * (xy - wz);
        o[2] = 2.f * (wy + xz);
        o[3] = 2.f * (wz + xy);
        o[4] = w2 - x2 + y2 - z2 - 1.0f;
        o[5] = 2.f * (yz - wx);
        o[6] = 2.f * (xz - wy);
        o[7] = 2.f * (wx + yz);
        o[8] = w2 - x2 - y2 + z2 - 1.0f;
#pragma unroll
        for (int e = 0; e < 9; e++)
            pff[(9 * i + e) * 64 + bl] = o[e];
    }
    __syncthreads();

    // ---- kinematic chain: 192 threads, one per (batch, row k) -> Amat ----
    if (t < 192) {
        int bl = t / 3, k = t - bl * 3;
        int b = b0 + bl;
        float w1 = dq[b * 4 + 0], x1 = dq[b * 4 + 1], y1 = dq[b * 4 + 2], z1 = dq[b * 4 + 3];
        float w2q = iq[0], x2q = iq[1], y2q = iq[2], z2q = iq[3];
        float qw = w1 * w2q - x1 * x2q - y1 * y2q - z1 * z2q;
        float qx = w1 * x2q + x1 * w2q + y1 * z2q - z1 * y2q;
        float qy = w1 * y2q - x1 * z2q + y1 * w2q + z1 * x2q;
        float qz = w1 * z2q + x1 * y2q - y1 * x2q + z1 * w2q;
        float qn = rsqrtf(qw * qw + qx * qx + qy * qy + qz * qz);
        qw *= qn; qx *= qn; qy *= qn; qz *= qn;
        float W2_ = qw * qw, X2 = qx * qx, Y2 = qy * qy, Z2 = qz * qz;
        float WX = qw * qx, WY = qw * qy, WZ = qw * qz;
        float XY = qx * qy, XZ = qx * qz, YZ = qy * qz;
        float R[9];
        R[0] = W2_ + X2 - Y2 - Z2; R[1] = 2.f * (XY - WZ);    R[2] = 2.f * (WY + XZ);
        R[3] = 2.f * (WZ + XY);    R[4] = W2_ - X2 + Y2 - Z2; R[5] = 2.f * (YZ - WX);
        R[6] = 2.f * (XZ - WY);    R[7] = 2.f * (WX + YZ);    R[8] = W2_ - X2 - Y2 + Z2;

        float rr0 = R[3 * k + 0], rr1 = R[3 * k + 1], rr2 = R[3 * k + 2];
        float rt = Jks[k];
        float* Ao = Amat + bl * 196;
        {
            float jx = Jks[0], jy = Jks[1], jz = Jks[2];
            Ao[k * 3 + 0] = rr0; Ao[k * 3 + 1] = rr1; Ao[k * 3 + 2] = rr2;
            Ao[9 + k] = rt - (rr0 * jx + rr1 * jy + rr2 * jz);
        }
#pragma unroll
        for (int chn = 0; chn < 5; chn++) {
            float cr0 = rr0, cr1 = rr1, cr2 = rr2, ct = rt;
#pragma unroll
            for (int s = 0; s < 3; s++) {
                int i = chn * 3 + 1 + s;
                int p = (s == 0) ? 0 : (i - 1);
                float Ri[9];
#pragma unroll
                for (int e = 0; e < 9; e++)
                    Ri[e] = pff[(9 * (i - 1) + e) * 64 + bl]
                          + ((e == 0 || e == 4 || e == 8) ? 1.0f : 0.0f);
                float rx = Jks[3 * i + 0] - Jks[3 * p + 0];
                float ry = Jks[3 * i + 1] - Jks[3 * p + 1];
                float rz = Jks[3 * i + 2] - Jks[3 * p + 2];
                float n0 = cr0 * Ri[0] + cr1 * Ri[3] + cr2 * Ri[6];
                float n1 = cr0 * Ri[1] + cr1 * Ri[4] + cr2 * Ri[7];
                float n2 = cr0 * Ri[2] + cr1 * Ri[5] + cr2 * Ri[8];
                float nt = cr0 * rx + cr1 * ry + cr2 * rz + ct;
                float jx = Jks[3 * i + 0], jy = Jks[3 * i + 1], jz = Jks[3 * i + 2];
                float* Aoi = Ao + i * 12;
                Aoi[k * 3 + 0] = n0; Aoi[k * 3 + 1] = n1; Aoi[k * 3 + 2] = n2;
                Aoi[9 + k] = nt - (n0 * jx + n1 * jy + n2 * jz);
                cr0 = n0; cr1 = n1; cr2 = n2; ct = nt;
            }
        }
    }
    __syncthreads();    // pff/ths dead

    // ---- GEMM + epilogue chunks ----
    int wm = wid >> 2, wn = wid & 3;
    int mbase = wm * 32, nbase = wn * 16;
    uint32_t aoff = (uint32_t)((mbase + (lane & 15)) * PROW + ((lane >> 4) & 1) * 16);
    uint32_t boff = (uint32_t)((nbase + (lane & 7) + ((lane >> 4) & 1) * 8) * PROW
                               + ((lane >> 3) & 1) * 16);
    uint32_t sAH = s2u(AH) + aoff, sAL = s2u(AL) + aoff;
    uint32_t sBH = s2u(BH) + boff, sBL = s2u(BL) + boff;
    int gid = lane >> 2, tig = lane & 3;
    int blE = t / 3, kkE = t - 3 * blE;    // epilogue ownership (t < 192)

    for (int nc = 0; nc < 16; nc++) {
        int n0c = nc * 64;
        // stage B chunk
        for (int i = t; i < 64 * 18; i += 256) {
            int r = i / 18, c = i - r * 18;
            uint32_t so = (uint32_t)(r * PROW + c * 16);
            uint64_t gb = (uint64_t)(n0c + r) * PFK + c * 8;
            *(uint4*)(BH + so) = *(const uint4*)&g_DhT[gb];
            *(uint4*)(BL + so) = *(const uint4*)&g_DlT[gb];
        }
        __syncthreads();

        // MMA: warp tile 32 x 16
        float acc[2][2][4];
#pragma unroll
        for (int mi = 0; mi < 2; mi++)
#pragma unroll
            for (int ni = 0; ni < 2; ni++)
#pragma unroll
                for (int e = 0; e < 4; e++) acc[mi][ni][e] = 0.f;
#pragma unroll
        for (int ks = 0; ks < 9; ks++) {
            uint32_t ka = (uint32_t)(ks * 32);
            uint32_t Ah[2][4], Al[2][4], Bh[4], Bl[4];
            ldm4(Ah[0], sAH + ka);
            ldm4(Ah[1], sAH + 16 * PROW + ka);
            ldm4(Al[0], sAL + ka);
            ldm4(Al[1], sAL + 16 * PROW + ka);
            ldm4(Bh, sBH + ka);
            ldm4(Bl, sBL + ka);
#pragma unroll
            for (int mi = 0; mi < 2; mi++) {
#pragma unroll
                for (int hf = 0; hf < 2; hf++) {
                    float* c = acc[mi][hf];
                    mmabf(c, Ah[mi], Bh[2 * hf], Bh[2 * hf + 1]);
                    mmabf(c, Ah[mi], Bl[2 * hf], Bl[2 * hf + 1]);
                    mmabf(c, Al[mi], Bh[2 * hf], Bh[2 * hf + 1]);
                }
            }
        }
        // spill chunk P to smem
#pragma unroll
        for (int mi = 0; mi < 2; mi++) {
            int row = mbase + mi * 16 + gid;
#pragma unroll
            for (int ni = 0; ni < 2; ni++) {
                int col = nbase + ni * 8 + tig * 2;
                const float* c = acc[mi][ni];
                *(float2*)&Ps[row * 68 + col] = make_float2(c[0], c[1]);
                *(float2*)&Ps[(row + 8) * 68 + col] = make_float2(c[2], c[3]);
            }
        }
        __syncthreads();

        // epilogue partial contraction
        if (t < 192) {
            const float* Pb = Ps + blE * 68;
            const float* Ab = Amat + blE * 196;
            int m = n0c / 3, c = n0c - 3 * (n0c / 3);
            int jo = m >> 4;
            float s = 0.f;
            int lim = (n0c + 64 > NN) ? (NN - n0c) : 64;
            for (int cl = 0; cl < lim; cl++) {
                s += Ab[(m & 15) * 12 + kkE * 3 + c] * Pb[cl];
                if (++c == 3) {
                    c = 0; m++;
                    int njo = m >> 4;
                    if (njo != jo) {
                        Js[blE * 64 + jo * 3 + kkE] += s;
                        s = 0.f; jo = njo;
                    }
                }
            }
            if (jo < NJO) Js[blE * 64 + jo * 3 + kkE] += s;
        }
        __syncthreads();
    }

    // ---- final writeout: joints = Js + M*t + trans ----
    if (t < 192) {
        const float* Ab = Amat + blE * 196;
        float tcom = Ts[blE * 3 + kkE];
        for (int jo = 0; jo < NJO; jo++) {
            float s = Js[blE * 64 + jo * 3 + kkE] + tcom;
#pragma unroll
            for (int j = 0; j < 16; j++)
                s += Ms[jo * 16 + j] * Ab[j * 12 + 9 + kkE];
            out[(b0 + blE) * 63 + jo * 3 + kkE] = s;
        }
    }
}

// ---------------- launcher ----------------
extern "C" void kernel_launch(void* const* d_in, const int* in_sizes, int n_in,
                              void* d_out, int out_size) {
    const float* theta = (const float*)d_in[0];
    const float* dq    = (const float*)d_in[1];
    const float* us    = (const float*)d_in[2];
    const float* iq    = (const float*)d_in[3];
    const float* tr    = (const float*)d_in[4];
    const float* vt    = (const float*)d_in[5];
    const float* sd    = (const float*)d_in[6];
    const float* Jr    = (const float*)d_in[7];
    const float* pd    = (const float*)d_in[8];
    const float* wg    = (const float*)d_in[9];
    float* out = (float*)d_out;

    cudaFuncSetAttribute(k_giant, cudaFuncAttributeMaxDynamicSharedMemorySize, G_SMEM);

    k_A<<<25 + PP_BLKS + (BATCH * 16) / 256, 256>>>(us, sd, vt, Jr, wg, pd, theta);
    k_B<<<NM + 63 + 143 * KSPLIT, 256>>>(Jr);
    k_red2<<<(136 * 1024) / 256, 256>>>();
    k_giant<<<128, 256, G_SMEM>>>(theta, dq, iq, tr, out);
}

// round 17
// speedup vs baseline: 1.4869x; 1.4869x over previous
#include <cuda_runtime.h>
#include <math.h>
#include <cstdint>

#define BATCH 8192
#define NVRT  778
#define NJO   21
#define NF    135
#define NM    336      /* 21*16 */
#define NN    1008     /* NM*3  */
#define NNP   1024
#define NFC   405      /* NF*3  */
#define PPLD  784
#define KSPLIT 8
#define KSEG  98       /* PPLD / KSPLIT */

#define BT    28       /* batches per fused tile */
#define NTILE 293      /* ceil(8192/28) */

// ---------------- scratch (__device__ globals; zero-init; padding never written) ----
__device__ float g_vsh[NVRT * 3];
__device__ float g_Jk[64];
__device__ float g_W2T[NM * PPLD];       // [m][v], rows padded to 784 (tail stays 0)
__device__ float g_Pp[NFC * PPLD];       // [fc][v], tail stays 0
__device__ float g_M[NM];
__device__ float g_C0[NNP];              // [1008..1024) stays 0
__device__ float g_Dp[KSPLIT * NF * NNP];// split-K partials (padding never written -> 0)
__device__ float g_Dd[(NF + 1) * NNP * 2]; // D rows 0..134 + C0 row 135, each value DUPLICATED
                                           // (padding n in [1008,1024) never written -> 0)

// ---------------- f32x2 helpers ----------------
typedef unsigned long long u64;
typedef ulonglong2 uv2;
__device__ __forceinline__ u64 pk2(float x, float y) {
    u64 r; asm("mov.b64 %0, {%1, %2};" : "=l"(r) : "f"(x), "f"(y)); return r;
}
__device__ __forceinline__ void upk2(u64 v, float& x, float& y) {
    asm("mov.b64 {%0, %1}, %2;" : "=f"(x), "=f"(y) : "l"(v));
}
__device__ __forceinline__ u64 fma2(u64 a, u64 b, u64 c) {
    u64 d; asm("fma.rn.f32x2 %0, %1, %2, %3;" : "=l"(d) : "l"(a), "l"(b), "l"(c)); return d;
}

// ================ stage A: vsh + W2T (25 blocks)  ||  Pp transpose (1231 blocks) ========
#define PP_BLKS ((NFC * NVRT + 255) / 256)
__global__ void k_A(const float* __restrict__ us, const float* __restrict__ sd,
                    const float* __restrict__ vt, const float* __restrict__ Jr,
                    const float* __restrict__ wg, const float* __restrict__ pd) {
    int t = threadIdx.x;
    if (blockIdx.x < 25) {
        __shared__ float jrs[32 * 21];
        __shared__ float wgs[32 * 17];
        int v0 = blockIdx.x * 32;
        int nv = NVRT - v0; if (nv > 32) nv = 32;
        for (int i = t; i < nv * 21; i += 256) jrs[i] = Jr[v0 * 21 + i];
        for (int i = t; i < nv * 16; i += 256) {
            int vl = i >> 4, j = i & 15;
            wgs[vl * 17 + j] = wg[(v0 + vl) * 16 + j];
        }
        for (int i = t; i < nv * 3; i += 256) {
            int g = v0 * 3 + i;
            float s = vt[g];
#pragma unroll
            for (int q = 0; q < 10; q++) s += us[q] * sd[q * 2334 + g];
            g_vsh[g] = s;
        }
        __syncthreads();
        for (int i = t; i < NM * 32; i += 256) {
            int vl = i & 31, m = i >> 5;
            int v = v0 + vl;
            if (v < NVRT)
                g_W2T[m * PPLD + v] = jrs[vl * 21 + (m >> 4)] * wgs[vl * 17 + (m & 15)];
        }
    } else {
        int idx = (blockIdx.x - 25) * 256 + t;
        if (idx < NFC * NVRT) {
            int fc = idx / NVRT, v = idx - fc * NVRT;
            int f = fc / 3, c = fc - 3 * f;
            g_Pp[fc * PPLD + v] = pd[f * 2334 + 3 * v + c];
        }
    }
}

// ================ stage B: Jk/M/C0 (399 blocks)  ||  D split-K partials ====
__global__ void k_B(const float* __restrict__ Jr) {
    int t = threadIdx.x;
    int blk = blockIdx.x;
    if (blk < NM + 63) {
        __shared__ float vs[NVRT * 3];
        __shared__ float red[4][256];
        for (int i = t; i < NVRT * 3; i += 256) vs[i] = g_vsh[i];
        __syncthreads();
        if (blk < NM) {
            int m = blk;
            float sm = 0.f, s0 = 0.f, s1 = 0.f, s2 = 0.f;
            for (int v = t; v < NVRT; v += 256) {
                float w = g_W2T[m * PPLD + v];
                sm += w;
                s0 += w * vs[v * 3 + 0];
                s1 += w * vs[v * 3 + 1];
                s2 += w * vs[v * 3 + 2];
            }
            red[0][t] = sm; red[1][t] = s0; red[2][t] = s1; red[3][t] = s2;
            __syncthreads();
            for (int o = 128; o > 0; o >>= 1) {
                if (t < o) {
                    red[0][t] += red[0][t + o]; red[1][t] += red[1][t + o];
                    red[2][t] += red[2][t + o]; red[3][t] += red[3][t + o];
                }
                __syncthreads();
            }
            if (t == 0) {
                g_M[m] = red[0][0];
                g_C0[m * 3 + 0] = red[1][0];
                g_C0[m * 3 + 1] = red[2][0];
                g_C0[m * 3 + 2] = red[3][0];
            }
        } else {
            int idx = blk - NM;
            int j = idx / 3, c = idx - 3 * j;
            float s = 0.f;
            for (int v = t; v < NVRT; v += 256) s += vs[v * 3 + c] * Jr[v * 21 + j];
            red[0][t] = s; __syncthreads();
            for (int o = 128; o > 0; o >>= 1) {
                if (t < o) red[0][t] += red[0][t + o];
                __syncthreads();
            }
            if (t == 0) g_Jk[j * 3 + c] = red[0][0];
        }
    } else {
        __shared__ float As[32][33];
        __shared__ float Bs[32][33];
        int b2 = blk - (NM + 63);
        int ks = b2 / 143;
        int rem = b2 - ks * 143;
        int m0 = (rem % 11) * 32;
        int fc0 = (rem / 11) * 32;
        int kbase = ks * KSEG, kend = kbase + KSEG;
        int tx = t & 15, ty = t >> 4;
        float acc[2][2] = {};
        for (int k0 = kbase; k0 < kend; k0 += 32) {
#pragma unroll
            for (int r = 0; r < 4; r++) {
                int e = t + 256 * r; int kk = e & 31, fl = e >> 5;
                int fc = fc0 + fl, k = k0 + kk;
                As[fl][kk] = (fc < NFC && k < kend) ? g_Pp[fc * PPLD + k] : 0.f;
            }
#pragma unroll
            for (int r = 0; r < 4; r++) {
                int e = t + 256 * r; int kk = e & 31, ml = e >> 5;
                int m = m0 + ml, k = k0 + kk;
                Bs[ml][kk] = (m < NM && k < kend) ? g_W2T[m * PPLD + k] : 0.f;
            }
            __syncthreads();
#pragma unroll
            for (int kk = 0; kk < 32; kk++) {
                float a0 = As[ty][kk], a1 = As[ty + 16][kk];
                float b0 = Bs[tx][kk], b1 = Bs[tx + 16][kk];
                acc[0][0] += a0 * b0; acc[0][1] += a0 * b1;
                acc[1][0] += a1 * b0; acc[1][1] += a1 * b1;
            }
            __syncthreads();
        }
#pragma unroll
        for (int i = 0; i < 2; i++) {
            int fc = fc0 + ty + 16 * i;
            if (fc >= NFC) continue;
            int f = fc / 3, c = fc - 3 * f;
#pragma unroll
            for (int jj = 0; jj < 2; jj++) {
                int m = m0 + tx + 16 * jj;
                if (m < NM) g_Dp[(ks * NF + f) * NNP + m * 3 + c] = acc[i][jj];
            }
        }
    }
}

// ================ stage C: combine split-K partials, write DUPLICATED ================
__global__ void k_red() {
    int idx = blockIdx.x * 256 + threadIdx.x;   // (NF+1)*NNP exact
    int k = idx >> 10, n = idx & 1023;
    float s;
    if (k < NF) {
        const int S = NF * NNP;
        s = 0.f;
#pragma unroll
        for (int q = 0; q < KSPLIT; q++) s += g_Dp[q * S + k * NNP + n];
    } else {
        s = g_C0[n];
    }
    g_Dd[idx * 2] = s;
    g_Dd[idx * 2 + 1] = s;
}

// ================ fused: pose features + chain + GEMM + epilogue ================
// 256 threads, 28 batches (14 pairs) per tile, grid 293.
// Thread t owns n = 4t..4t+3 (spill active t < 252) and ALL 14 batch-pairs.
// GEMM inner loop: depth-4 D prefetch (2x LDG.128 of PRE-DUPLICATED pairs -> zero MOVs)
// + 1-row pf double buffer (LDS) covering the 29-cyc LDS RAW with 56 fma2.
// smem float layout:
//   Ps  [0 .. 28224)      28 x 1008  (aliased early: ths [0..1260), pfp [1264..5584))
//   Asm [28224 .. 33600)  28 x 192
//   Ms  [33600 .. 33936)
//   Ts  [33936 .. 34032)
//   Jks [34032 .. 34080)
// pfp: per f, 128 B = 16 u64 slots; slot pr (0..13) = batches (2pr, 2pr+1) packed.
#define SMEM_BYTES (34080 * 4)

__device__ __forceinline__ void ldsrow(u64 (&p)[14], unsigned sp) {
#pragma unroll
    for (int q = 0; q < 7; q++)
        asm("ld.shared.v2.u64 {%0, %1}, [%2];"
            : "=l"(p[2 * q]), "=l"(p[2 * q + 1]) : "r"(sp + q * 16));
}

__device__ __forceinline__ void ldrow4(u64 (&d)[4], const uv2* ptr) {
    uv2 a = ptr[0], b = ptr[1];
    d[0] = a.x; d[1] = a.y; d[2] = b.x; d[3] = b.y;
}

__device__ __forceinline__ void fmarow(const u64 (&d)[4], const u64 (&p)[14],
                                       u64 (&acc)[4][14]) {
#pragma unroll
    for (int j = 0; j < 14; j++) {
        acc[0][j] = fma2(d[0], p[j], acc[0][j]);
        acc[1][j] = fma2(d[1], p[j], acc[1][j]);
        acc[2][j] = fma2(d[2], p[j], acc[2][j]);
        acc[3][j] = fma2(d[3], p[j], acc[3][j]);
    }
}

__global__ __launch_bounds__(256, 1)
void k_fused(const float* __restrict__ theta, const float* __restrict__ dq,
             const float* __restrict__ iq, const float* __restrict__ tr,
             float* __restrict__ out) {
    extern __shared__ float sm[];
    float* Ps  = sm;
    float* Asm = sm + 28224;
    float* Ms  = sm + 33600;
    float* Ts  = sm + 33936;
    float* Jks = sm + 34032;
    float* ths = sm;                 // alias (dead before Ps writes)
    u64*  pfp  = (u64*)(sm + 1264);  // alias (dead before Ps writes); 16B aligned
    float* pff = sm + 1264;          // float view of pfp

    int t = threadIdx.x;
    int b0 = blockIdx.x * BT;
    int nb = BATCH - b0; if (nb > BT) nb = BT;   // 28, or 16 for last tile

    // ---- stage inputs (guarded by nb) ----
    for (int i = t; i < nb * 45; i += 256) ths[i] = theta[b0 * 45 + i];
    if (t >= 96 && t < 144) { int i = t - 96; Jks[i] = g_Jk[i]; }
    for (int i = t; i < NM; i += 256) Ms[i] = g_M[i];
    if (t < nb * 3) Ts[t] = tr[b0 * 3 + t];
    __syncthreads();

    // ---- pose features: nb*15 items (<=420), loop over 256 threads ----
    for (int it = t; it < nb * 15; it += 256) {
        int bl = it / 15, i = it - bl * 15;
        const float* th = ths + bl * 45 + 3 * i;
        float tx = th[0], ty = th[1], tz = th[2];
        float ax = tx + 1e-8f, ay = ty + 1e-8f, az = tz + 1e-8f;
        float angle = sqrtf(ax * ax + ay * ay + az * az);
        float inv = 1.0f / angle;
        float nx = tx * inv, ny = ty * inv, nz = tz * inv;
        float sh, ch;
        sincosf(0.5f * angle, &sh, &ch);
        float qw = ch, qx = sh * nx, qy = sh * ny, qz = sh * nz;
        float qn = rsqrtf(qw * qw + qx * qx + qy * qy + qz * qz);
        qw *= qn; qx *= qn; qy *= qn; qz *= qn;
        float w2 = qw * qw, x2 = qx * qx, y2 = qy * qy, z2 = qz * qz;
        float wx = qw * qx, wy = qw * qy, wz = qw * qz;
        float xy = qx * qy, xz = qx * qz, yz = qy * qz;
        float o[9];
        o[0] = w2 + x2 - y2 - z2 - 1.0f;
        o[1] = 2.f * (xy - wz);
        o[2] = 2.f * (wy + xz);
        o[3] = 2.f * (wz + xy);
        o[4] = w2 - x2 + y2 - z2 - 1.0f;
        o[5] = 2.f * (yz - wx);
        o[6] = 2.f * (xz - wy);
        o[7] = 2.f * (wx + yz);
        o[8] = w2 - x2 - y2 + z2 - 1.0f;
        int pr = bl >> 1, lo = bl & 1;
#pragma unroll
        for (int e = 0; e < 9; e++)
            pff[(9 * i + e) * 32 + pr * 2 + lo] = o[e];
    }
    __syncthreads();

    // ---- kinematic chain: nb*3 threads (<=84), one per (batch, row k) ----
    if (t < nb * 3) {
        int bl = t / 3, k = t - bl * 3;
        int b = b0 + bl;
        float w1 = dq[b * 4 + 0], x1 = dq[b * 4 + 1], y1 = dq[b * 4 + 2], z1 = dq[b * 4 + 3];
        float w2q = iq[0], x2q = iq[1], y2q = iq[2], z2q = iq[3];
        float qw = w1 * w2q - x1 * x2q - y1 * y2q - z1 * z2q;
        float qx = w1 * x2q + x1 * w2q + y1 * z2q - z1 * y2q;
        float qy = w1 * y2q - x1 * z2q + y1 * w2q + z1 * x2q;
        float qz = w1 * z2q + x1 * y2q - y1 * x2q + z1 * w2q;
        float qn = rsqrtf(qw * qw + qx * qx + qy * qy + qz * qz);
        qw *= qn; qx *= qn; qy *= qn; qz *= qn;
        float W2_ = qw * qw, X2 = qx * qx, Y2 = qy * qy, Z2 = qz * qz;
        float WX = qw * qx, WY = qw * qy, WZ = qw * qz;
        float XY = qx * qy, XZ = qx * qz, YZ = qy * qz;
        float R[9];
        R[0] = W2_ + X2 - Y2 - Z2; R[1] = 2.f * (XY - WZ);    R[2] = 2.f * (WY + XZ);
        R[3] = 2.f * (WZ + XY);    R[4] = W2_ - X2 + Y2 - Z2; R[5] = 2.f * (YZ - WX);
        R[6] = 2.f * (XZ - WY);    R[7] = 2.f * (WX + YZ);    R[8] = W2_ - X2 - Y2 + Z2;

        float rr0 = R[3 * k + 0], rr1 = R[3 * k + 1], rr2 = R[3 * k + 2];
        float rt = Jks[k];
        float* Ao = Asm + bl * 192;
        {
            float jx = Jks[0], jy = Jks[1], jz = Jks[2];
            Ao[k * 3 + 0] = rr0; Ao[k * 3 + 1] = rr1; Ao[k * 3 + 2] = rr2;
            Ao[9 + k] = rt - (rr0 * jx + rr1 * jy + rr2 * jz);
        }
        int pr = bl >> 1, lo = bl & 1;
#pragma unroll
        for (int chn = 0; chn < 5; chn++) {
            float cr0 = rr0, cr1 = rr1, cr2 = rr2, ct = rt;
#pragma unroll
            for (int s = 0; s < 3; s++) {
                int i = chn * 3 + 1 + s;
                int p = (s == 0) ? 0 : (i - 1);
                float Ri[9];
#pragma unroll
                for (int e = 0; e < 9; e++)
                    Ri[e] = pff[(9 * (i - 1) + e) * 32 + pr * 2 + lo]
                          + ((e == 0 || e == 4 || e == 8) ? 1.0f : 0.0f);
                float rx = Jks[3 * i + 0] - Jks[3 * p + 0];
                float ry = Jks[3 * i + 1] - Jks[3 * p + 1];
                float rz = Jks[3 * i + 2] - Jks[3 * p + 2];
                float n0 = cr0 * Ri[0] + cr1 * Ri[3] + cr2 * Ri[6];
                float n1 = cr0 * Ri[1] + cr1 * Ri[4] + cr2 * Ri[7];
                float n2 = cr0 * Ri[2] + cr1 * Ri[5] + cr2 * Ri[8];
                float nt = cr0 * rx + cr1 * ry + cr2 * rz + ct;
                float jx = Jks[3 * i + 0], jy = Jks[3 * i + 1], jz = Jks[3 * i + 2];
                float* Aoi = Ao + i * 12;
                Aoi[k * 3 + 0] = n0; Aoi[k * 3 + 1] = n1; Aoi[k * 3 + 2] = n2;
                Aoi[9 + k] = nt - (n0 * jx + n1 * jy + n2 * jz);
                cr0 = n0; cr1 = n1; cr2 = n2; ct = nt;
            }
        }
    }

    // ---- main GEMM: n = 4t..4t+3, 14 pairs, depth-4 dup-D prefetch + pf double buffer --
    u64 acc[4][14];
    {
        u64 cc[4];
        ldrow4(cc, (const uv2*)(g_Dd + NF * NNP * 2 + 8 * t));   // C0 row, duplicated
#pragma unroll
        for (int p = 0; p < 14; p++) {
            acc[0][p] = cc[0]; acc[1][p] = cc[1]; acc[2][p] = cc[2]; acc[3][p] = cc[3];
        }
    }
    const uv2* dl = (const uv2*)(g_Dd + 8 * t);    // row r at dl[r*512]
    u64 dbuf[4][4];
    ldrow4(dbuf[0], dl);
    ldrow4(dbuf[1], dl + 512);
    ldrow4(dbuf[2], dl + 1024);
    ldrow4(dbuf[3], dl + 1536);
    dl += 2048;                                     // points at row 4

    unsigned sp = (unsigned)__cvta_generic_to_shared(pfp);  // per-f stride 128 B

    u64 pA[14], pB[14];
    ldsrow(pA, sp);                                 // pf row 0

    for (int f0 = 0; f0 < 128; f0 += 4) {
        u64 dc[4];
#pragma unroll
        for (int e = 0; e < 4; e++) dc[e] = dbuf[0][e];
        ldrow4(dbuf[0], dl);          ldsrow(pB, sp + 128); fmarow(dc, pA, acc);
#pragma unroll
        for (int e = 0; e < 4; e++) dc[e] = dbuf[1][e];
        ldrow4(dbuf[1], dl + 512);    ldsrow(pA, sp + 256); fmarow(dc, pB, acc);
#pragma unroll
        for (int e = 0; e < 4; e++) dc[e] = dbuf[2][e];
        ldrow4(dbuf[2], dl + 1024);   ldsrow(pB, sp + 384); fmarow(dc, pA, acc);
#pragma unroll
        for (int e = 0; e < 4; e++) dc[e] = dbuf[3][e];
        ldrow4(dbuf[3], dl + 1536);   ldsrow(pA, sp + 512); fmarow(dc, pB, acc);
        dl += 2048;
        sp += 512;
    }
    // state: pA = pf row 128, dbuf = D rows 128..131, dl -> row 132, sp -> row 128
    {
        u64 dc[4];
#pragma unroll
        for (int e = 0; e < 4; e++) dc[e] = dbuf[0][e];
        ldrow4(dbuf[0], dl);          ldsrow(pB, sp + 128); fmarow(dc, pA, acc); // f=128
#pragma unroll
        for (int e = 0; e < 4; e++) dc[e] = dbuf[1][e];
        ldrow4(dbuf[1], dl + 512);    ldsrow(pA, sp + 256); fmarow(dc, pB, acc); // f=129
#pragma unroll
        for (int e = 0; e < 4; e++) dc[e] = dbuf[2][e];
        ldrow4(dbuf[2], dl + 1024);   ldsrow(pB, sp + 384); fmarow(dc, pA, acc); // f=130
#pragma unroll
        for (int e = 0; e < 4; e++) dc[e] = dbuf[3][e];
                                      ldsrow(pA, sp + 512); fmarow(dc, pB, acc); // f=131
#pragma unroll
        for (int e = 0; e < 4; e++) dc[e] = dbuf[0][e];
                                      ldsrow(pB, sp + 640); fmarow(dc, pA, acc); // f=132
#pragma unroll
        for (int e = 0; e < 4; e++) dc[e] = dbuf[1][e];
                                      ldsrow(pA, sp + 768); fmarow(dc, pB, acc); // f=133
#pragma unroll
        for (int e = 0; e < 4; e++) dc[e] = dbuf[2][e];
                                                            fmarow(dc, pA, acc); // f=134
    }
    __syncthreads();   // pfp/ths now dead

    // ---- spill P to smem ----
    if (t < 252) {
#pragma unroll
        for (int p = 0; p < 14; p++) {
            int bg = 2 * p;
#pragma unroll
            for (int k = 0; k < 4; k++) {
                float x0, x1;
                upk2(acc[k][p], x0, x1);
                Ps[bg * NN + 4 * t + k] = x0;
                Ps[(bg + 1) * NN + 4 * t + k] = x1;
            }
        }
    }
    __syncthreads();

    // ---- epilogue: joints = A ∘ P + M*t + trans ----
    for (int idx = t; idx < nb * 63; idx += 256) {
        int bl = idx / 63;
        int r = idx - bl * 63;
        int jo = r / 3;
        int k = r - jo * 3;
        const float* Ab = Asm + bl * 192;
        const float* Pb = Ps + bl * NN;
        float s = Ts[bl * 3 + k];
#pragma unroll
        for (int j = 0; j < 16; j++) {
            int rb = j * 12 + k * 3;
            int pb = (jo * 16 + j) * 3;
            s += Ab[rb] * Pb[pb] + Ab[rb + 1] * Pb[pb + 1] + Ab[rb + 2] * Pb[pb + 2]
               + Ms[jo * 16 + j] * Ab[j * 12 + 9 + k];
        }
        out[(b0 + bl) * 63 + jo * 3 + k] = s;
    }
}

// ---------------- launcher ----------------
extern "C" void kernel_launch(void* const* d_in, const int* in_sizes, int n_in,
                              void* d_out, int out_size) {
    const float* theta = (const float*)d_in[0];
    const float* dq    = (const float*)d_in[1];
    const float* us    = (const float*)d_in[2];
    const float* iq    = (const float*)d_in[3];
    const float* tr    = (const float*)d_in[4];
    const float* vt    = (const float*)d_in[5];
    const float* sd    = (const float*)d_in[6];
    const float* Jr    = (const float*)d_in[7];
    const float* pd    = (const float*)d_in[8];
    const float* wg    = (const float*)d_in[9];
    float* out = (float*)d_out;

    cudaFuncSetAttribute(k_fused, cudaFuncAttributeMaxDynamicSharedMemorySize, SMEM_BYTES);

    k_A<<<25 + PP_BLKS, 256>>>(us, sd, vt, Jr, wg, pd);
    k_B<<<NM + 63 + 143 * KSPLIT, 256>>>(Jr);
    k_red<<<((NF + 1) * NNP) / 256, 256>>>();
    k_fused<<<NTILE, 256, SMEM_BYTES>>>(theta, dq, iq, tr, out);
}